// round 4
// baseline (speedup 1.0000x reference)
#include <cuda_runtime.h>
#include <cstdint>

// Problem constants (fixed by the reference)
#define B_DIM 1024
#define T_DIM 256
#define D_DIM 1024
#define NUM_LABELS 8
#define NUM_PROTOS 64   // per label; M = 512 total

#define T_CHUNK 64
#define N_CHUNKS (T_DIM / T_CHUNK)       // 4
#define N_TILES  (B_DIM * N_CHUNKS)      // 4096 tiles x 256 KB contiguous
#define GRID_P1  1184                    // 148 SMs x 8 resident CTAs

// Device scratch (no cudaMalloc allowed)
__device__ float g_c[NUM_LABELS * D_DIM];   // c_l[d] = mean_p w[8p+l][d]
__device__ float g_sqpart[NUM_LABELS * 4];
__device__ unsigned g_ticket;               // stealing counter (memset each launch)
__device__ float4 g_scratch[(size_t)N_TILES * (D_DIM / 4)];  // 16 MB partials

// ---------------------------------------------------------------------------
// Prep: fold prototype_weight [512,1024] -> c[8][1024], sqpart[32].
// Overlapped under phase 1 via PDL (only phase 2 consumes these).
// ---------------------------------------------------------------------------
__global__ void proto_fold_kernel(const float* __restrict__ w) {
    const int l     = blockIdx.x >> 2;
    const int chunk = blockIdx.x & 3;
    const int d     = chunk * 256 + threadIdx.x;

    float sum = 0.0f, sq = 0.0f;
#pragma unroll 8
    for (int p = 0; p < NUM_PROTOS; ++p) {
        float v = w[(size_t)((p << 3) + l) * D_DIM + d];
        sum += v;
        sq  += v * v;
    }
    g_c[l * D_DIM + d] = sum * (1.0f / NUM_PROTOS);

    __shared__ float red[256];
    red[threadIdx.x] = sq;
    __syncthreads();
    for (int s = 128; s > 0; s >>= 1) {
        if (threadIdx.x < s) red[threadIdx.x] += red[threadIdx.x + s];
        __syncthreads();
    }
    if (threadIdx.x == 0) g_sqpart[blockIdx.x] = red[0];
}

// ---------------------------------------------------------------------------
// Phase 1: dynamic work-stealing pooling. Tile = (b, t-chunk of 64 rows),
// a fully CONTIGUOUS 256 KB stream. Each block pulls tiles from g_ticket
// until exhausted, storing a 1024-float partial sum per tile to g_scratch.
// Fixed scratch slot per tile -> deterministic regardless of which SM ran it.
// ---------------------------------------------------------------------------
__global__ __launch_bounds__(256, 8)
void pool_phase1_kernel(const float* __restrict__ h) {
    const int tid = threadIdx.x;
    const float4* __restrict__ h4 = reinterpret_cast<const float4*>(h);
    __shared__ unsigned s_tile;

    for (;;) {
        __syncthreads();   // protect s_tile reuse across iterations
        if (tid == 0) s_tile = atomicAdd(&g_ticket, 1u);
        __syncthreads();
        const unsigned tile = s_tile;
        if (tile >= N_TILES) return;

        const int b = tile >> 2;       // batch row
        const int c = tile & 3;        // t-chunk
        const float4* hp = h4 + ((size_t)b * T_DIM + c * T_CHUNK) * (D_DIM / 4) + tid;

        float4 s0 = {0,0,0,0}, s1 = {0,0,0,0}, s2 = {0,0,0,0}, s3 = {0,0,0,0};
#pragma unroll 2
        for (int t = 0; t < T_CHUNK; t += 8) {
            float4 v0 = __ldcs(hp + (size_t)(t + 0) * 256);
            float4 v1 = __ldcs(hp + (size_t)(t + 1) * 256);
            float4 v2 = __ldcs(hp + (size_t)(t + 2) * 256);
            float4 v3 = __ldcs(hp + (size_t)(t + 3) * 256);
            float4 v4 = __ldcs(hp + (size_t)(t + 4) * 256);
            float4 v5 = __ldcs(hp + (size_t)(t + 5) * 256);
            float4 v6 = __ldcs(hp + (size_t)(t + 6) * 256);
            float4 v7 = __ldcs(hp + (size_t)(t + 7) * 256);
            s0.x += v0.x; s0.y += v0.y; s0.z += v0.z; s0.w += v0.w;
            s1.x += v1.x; s1.y += v1.y; s1.z += v1.z; s1.w += v1.w;
            s2.x += v2.x; s2.y += v2.y; s2.z += v2.z; s2.w += v2.w;
            s3.x += v3.x; s3.y += v3.y; s3.z += v3.z; s3.w += v3.w;
            s0.x += v4.x; s0.y += v4.y; s0.z += v4.z; s0.w += v4.w;
            s1.x += v5.x; s1.y += v5.y; s1.z += v5.z; s1.w += v5.w;
            s2.x += v6.x; s2.y += v6.y; s2.z += v6.z; s2.w += v6.w;
            s3.x += v7.x; s3.y += v7.y; s3.z += v7.z; s3.w += v7.w;
        }

        float4 r;
        r.x = (s0.x + s1.x) + (s2.x + s3.x);
        r.y = (s0.y + s1.y) + (s2.y + s3.y);
        r.z = (s0.z + s1.z) + (s2.z + s3.z);
        r.w = (s0.w + s1.w) + (s2.w + s3.w);
        g_scratch[(size_t)tile * (D_DIM / 4) + tid] = r;
    }
}

// ---------------------------------------------------------------------------
// Phase 2: per row b, combine the 4 t-chunk partials (fixed order ->
// deterministic), then epilogue: out[b,l] = 2 a.c_l - ||a||^2 - s_l.
// Reads 16 KB scratch + 32 KB c per block, largely L2-resident.
// ---------------------------------------------------------------------------
__global__ __launch_bounds__(256, 8)
void phase2_kernel(float* __restrict__ out) {
    const int b   = blockIdx.x;
    const int tid = threadIdx.x;

    const float4* sp = g_scratch + (size_t)b * N_CHUNKS * (D_DIM / 4) + tid;
    float4 p0 = sp[0 * 256], p1 = sp[1 * 256], p2 = sp[2 * 256], p3 = sp[3 * 256];

    const float inv_t = 1.0f / T_DIM;
    float4 a;
    a.x = ((p0.x + p1.x) + (p2.x + p3.x)) * inv_t;
    a.y = ((p0.y + p1.y) + (p2.y + p3.y)) * inv_t;
    a.z = ((p0.z + p1.z) + (p2.z + p3.z)) * inv_t;
    a.w = ((p0.w + p1.w) + (p2.w + p3.w)) * inv_t;

    float asq = a.x * a.x + a.y * a.y + a.z * a.z + a.w * a.w;

    float dot[NUM_LABELS];
#pragma unroll
    for (int l = 0; l < NUM_LABELS; ++l) {
        float4 cv = reinterpret_cast<const float4*>(g_c + l * D_DIM)[tid];
        dot[l] = a.x * cv.x + a.y * cv.y + a.z * cv.z + a.w * cv.w;
    }

    const unsigned FULL = 0xFFFFFFFFu;
#pragma unroll
    for (int off = 16; off > 0; off >>= 1) {
        asq += __shfl_xor_sync(FULL, asq, off);
#pragma unroll
        for (int l = 0; l < NUM_LABELS; ++l)
            dot[l] += __shfl_xor_sync(FULL, dot[l], off);
    }

    __shared__ float part[8][12];
    const int wid = tid >> 5;
    if ((tid & 31) == 0) {
#pragma unroll
        for (int l = 0; l < NUM_LABELS; ++l) part[wid][l] = dot[l];
        part[wid][8] = asq;
    }
    __syncthreads();

    if (tid < NUM_LABELS) {
        const int l = tid;
        float dl = 0.0f, aq = 0.0f;
#pragma unroll
        for (int w = 0; w < 8; ++w) {
            dl += part[w][l];
            aq += part[w][8];
        }
        float sl = (g_sqpart[l * 4 + 0] + g_sqpart[l * 4 + 1] +
                    g_sqpart[l * 4 + 2] + g_sqpart[l * 4 + 3]) * (1.0f / NUM_PROTOS);
        out[(size_t)b * NUM_LABELS + l] = 2.0f * dl - aq - sl;
    }
}

extern "C" void kernel_launch(void* const* d_in, const int* in_sizes, int n_in,
                              void* d_out, int out_size) {
    const float* h = (const float*)d_in[0];   // hidden_states [B, T, D]
    const float* w = (const float*)d_in[1];   // prototype_weight [512, D]
    float* out = (float*)d_out;               // [B, 8]

    // Reset the stealing ticket (graph-capturable async memset; strictly
    // precedes the fold kernel, which strictly precedes phase-1's start
    // even under PDL).
    void* tick_addr = nullptr;
    cudaGetSymbolAddress(&tick_addr, g_ticket);
    cudaMemsetAsync(tick_addr, 0, sizeof(unsigned), 0);

    // Fold kernel (2 MB read) — overlapped under phase 1 via PDL.
    proto_fold_kernel<<<32, 256>>>(w);

    // Phase 1: persistent stealing grid with PDL so it starts during fold.
    cudaLaunchConfig_t cfg = {};
    cfg.gridDim  = dim3(GRID_P1);
    cfg.blockDim = dim3(256);
    cfg.dynamicSmemBytes = 0;
    cfg.stream = 0;

    cudaLaunchAttribute attrs[1];
    attrs[0].id = cudaLaunchAttributeProgrammaticStreamSerialization;
    attrs[0].val.programmaticStreamSerializationAllowed = 1;
    cfg.attrs = attrs;
    cfg.numAttrs = 1;

    cudaLaunchKernelEx(&cfg, pool_phase1_kernel, h);

    // Phase 2: stream-ordered after phase 1; consumes scratch + fold outputs.
    phase2_kernel<<<B_DIM, 256>>>(out);
}

// round 5
// speedup vs baseline: 1.0538x; 1.0538x over previous
#include <cuda_runtime.h>
#include <cstdint>

// Problem constants (fixed by the reference)
#define B_DIM 1024
#define T_DIM 256
#define D_DIM 1024
#define NUM_LABELS 8
#define NUM_PROTOS 64   // per label; M = 512 total

// Device scratch (no cudaMalloc allowed)
__device__ float g_c[NUM_LABELS * D_DIM];  // c_l[d] = mean_p w[8p+l][d]
__device__ float g_q[NUM_LABELS * D_DIM];  // q_l[d] = sum_p w[8p+l][d]^2
__device__ float g_s[NUM_LABELS];          // s_l = (1/64) sum_d q_l[d]
__device__ unsigned g_done[2];             // fold-done, s-done (memset per launch)

// ---------------------------------------------------------------------------
// Fused kernel. One block per batch row b = blockIdx.x. Phases:
//   A (all blocks, ~0.3us): distributed fold — warp j reduces the 64
//     prototypes of label j at column d=bid -> g_c, g_q. Fixed shuffle
//     order -> deterministic. Signal done[0].
//   B (blocks 0..7 only, ~0.5us): spin done[0]==1024, reduce g_q row l=bid
//     -> g_s[l]. Signal done[1].
//   C (all blocks, ~150us): stream row b (256 KB contiguous, __ldcs).
//   D (all blocks): spin done[1]==8 (satisfied ~149us ago -> zero wait),
//     epilogue: out[b,l] = 2*a.c_l - ||a||^2 - s_l.
// Grid 1024 <= 1184 residency (occ 8) -> single wave, spins are safe.
// ---------------------------------------------------------------------------
__global__ __launch_bounds__(256, 8)
void fused_pool_proto_kernel(const float* __restrict__ h,
                             const float* __restrict__ w,
                             float* __restrict__ out) {
    const int b    = blockIdx.x;
    const int tid  = threadIdx.x;
    const int wid  = tid >> 5;   // warp 0..7
    const int lane = tid & 31;
    const unsigned FULL = 0xFFFFFFFFu;

    // ---- Phase A: distributed fold, (l=wid, d=b) ----
    {
        // lane reduces p=lane and p=lane+32
        float v1 = w[(size_t)(((lane)      << 3) + wid) * D_DIM + b];
        float v2 = w[(size_t)(((lane + 32) << 3) + wid) * D_DIM + b];
        float sum = v1 + v2;
        float sq  = v1 * v1 + v2 * v2;
#pragma unroll
        for (int off = 16; off > 0; off >>= 1) {
            sum += __shfl_xor_sync(FULL, sum, off);
            sq  += __shfl_xor_sync(FULL, sq,  off);
        }
        if (lane == 0) {
            g_c[wid * D_DIM + b] = sum * (1.0f / NUM_PROTOS);
            g_q[wid * D_DIM + b] = sq;
        }
    }
    __threadfence();
    __syncthreads();
    if (tid == 0) atomicAdd(&g_done[0], 1u);

    // ---- Phase B: blocks 0..7 compute s_l ----
    if (b < NUM_LABELS) {
        if (tid == 0) {
            while (atomicAdd(&g_done[0], 0u) < (unsigned)B_DIM) {}
        }
        __syncthreads();
        __threadfence();
        float qs = g_q[b * D_DIM + tid] + g_q[b * D_DIM + 256 + tid]
                 + g_q[b * D_DIM + 512 + tid] + g_q[b * D_DIM + 768 + tid];
#pragma unroll
        for (int off = 16; off > 0; off >>= 1)
            qs += __shfl_xor_sync(FULL, qs, off);
        __shared__ float sred[8];
        if (lane == 0) sred[wid] = qs;
        __syncthreads();
        if (tid == 0) {
            float t = 0.0f;
#pragma unroll
            for (int ww = 0; ww < 8; ++ww) t += sred[ww];
            g_s[b] = t * (1.0f / NUM_PROTOS);
            __threadfence();
            atomicAdd(&g_done[1], 1u);
        }
        __syncthreads();
    }

    // ---- Phase C: stream row b (identical to the 154.9us R1 loop) ----
    const float4* hp = reinterpret_cast<const float4*>(h)
                       + (size_t)b * T_DIM * (D_DIM / 4) + tid;

    float4 s0 = {0,0,0,0}, s1 = {0,0,0,0}, s2 = {0,0,0,0}, s3 = {0,0,0,0};
#pragma unroll 4
    for (int t = 0; t < T_DIM; t += 8) {
        float4 v0 = __ldcs(hp + (size_t)(t + 0) * 256);
        float4 v1 = __ldcs(hp + (size_t)(t + 1) * 256);
        float4 v2 = __ldcs(hp + (size_t)(t + 2) * 256);
        float4 v3 = __ldcs(hp + (size_t)(t + 3) * 256);
        float4 v4 = __ldcs(hp + (size_t)(t + 4) * 256);
        float4 v5 = __ldcs(hp + (size_t)(t + 5) * 256);
        float4 v6 = __ldcs(hp + (size_t)(t + 6) * 256);
        float4 v7 = __ldcs(hp + (size_t)(t + 7) * 256);
        s0.x += v0.x; s0.y += v0.y; s0.z += v0.z; s0.w += v0.w;
        s1.x += v1.x; s1.y += v1.y; s1.z += v1.z; s1.w += v1.w;
        s2.x += v2.x; s2.y += v2.y; s2.z += v2.z; s2.w += v2.w;
        s3.x += v3.x; s3.y += v3.y; s3.z += v3.z; s3.w += v3.w;
        s0.x += v4.x; s0.y += v4.y; s0.z += v4.z; s0.w += v4.w;
        s1.x += v5.x; s1.y += v5.y; s1.z += v5.z; s1.w += v5.w;
        s2.x += v6.x; s2.y += v6.y; s2.z += v6.z; s2.w += v6.w;
        s3.x += v7.x; s3.y += v7.y; s3.z += v7.z; s3.w += v7.w;
    }

    const float inv_t = 1.0f / T_DIM;
    float4 a;
    a.x = (s0.x + s1.x + s2.x + s3.x) * inv_t;
    a.y = (s0.y + s1.y + s2.y + s3.y) * inv_t;
    a.z = (s0.z + s1.z + s2.z + s3.z) * inv_t;
    a.w = (s0.w + s1.w + s2.w + s3.w) * inv_t;

    float asq = a.x * a.x + a.y * a.y + a.z * a.z + a.w * a.w;

    // ---- Phase D: wait for fold results (zero actual wait), epilogue ----
    if (tid == 0) {
        while (atomicAdd(&g_done[1], 0u) < (unsigned)NUM_LABELS) {}
    }
    __syncthreads();
    __threadfence();

    float dot[NUM_LABELS];
#pragma unroll
    for (int l = 0; l < NUM_LABELS; ++l) {
        float4 cv = reinterpret_cast<const float4*>(g_c + l * D_DIM)[tid];
        dot[l] = a.x * cv.x + a.y * cv.y + a.z * cv.z + a.w * cv.w;
    }

#pragma unroll
    for (int off = 16; off > 0; off >>= 1) {
        asq += __shfl_xor_sync(FULL, asq, off);
#pragma unroll
        for (int l = 0; l < NUM_LABELS; ++l)
            dot[l] += __shfl_xor_sync(FULL, dot[l], off);
    }

    __shared__ float part[8][12];  // 8 warps x (8 dots + asq), padded
    if (lane == 0) {
#pragma unroll
        for (int l = 0; l < NUM_LABELS; ++l) part[wid][l] = dot[l];
        part[wid][8] = asq;
    }
    __syncthreads();

    if (tid < NUM_LABELS) {
        const int l = tid;
        float dl = 0.0f, aq = 0.0f;
#pragma unroll
        for (int ww = 0; ww < 8; ++ww) {
            dl += part[ww][l];
            aq += part[ww][8];
        }
        out[(size_t)b * NUM_LABELS + l] = 2.0f * dl - aq - g_s[l];
    }
}

extern "C" void kernel_launch(void* const* d_in, const int* in_sizes, int n_in,
                              void* d_out, int out_size) {
    const float* h = (const float*)d_in[0];   // hidden_states [B, T, D]
    const float* w = (const float*)d_in[1];   // prototype_weight [512, D]
    float* out = (float*)d_out;               // [B, 8]

    // Reset the two done-flags (graph-capturable async memset).
    void* done_addr = nullptr;
    cudaGetSymbolAddress(&done_addr, g_done);
    cudaMemsetAsync(done_addr, 0, 2 * sizeof(unsigned), 0);

    fused_pool_proto_kernel<<<B_DIM, 256>>>(h, w, out);
}

// round 6
// speedup vs baseline: 1.0737x; 1.0188x over previous
#include <cuda_runtime.h>
#include <cstdint>

// Problem constants (fixed by the reference)
#define B_DIM 1024
#define T_DIM 256
#define D_DIM 1024
#define NUM_LABELS 8
#define NUM_PROTOS 64   // per label; M = 512 total

// Device scratch (no cudaMalloc allowed)
__device__ float g_c[NUM_LABELS * D_DIM];   // c_l[d] = mean_p w[8p+l][d]   (32 KB)
__device__ float g_sqpart[NUM_LABELS * 4];  // partial sums of w^2 per (l, d-chunk)

// ---------------------------------------------------------------------------
// Prep: fold prototype_weight [512, 1024] into c[8][1024] and sqpart[8][4].
// Grid: 32 blocks (l = blk>>2, chunk = blk&3), 256 threads (one d each).
// Loads batched 16-wide (MLP=16) + __ldcg so the fold clears its SMs in
// ~2.5us instead of 9.3us -> displaced pool CTAs start sooner under PDL.
// Fixed summation order -> deterministic.
// ---------------------------------------------------------------------------
__global__ __launch_bounds__(256, 8)
void proto_fold_kernel(const float* __restrict__ w) {
    const int l     = blockIdx.x >> 2;
    const int chunk = blockIdx.x & 3;
    const int d     = chunk * 256 + threadIdx.x;

    float sum = 0.0f, sq = 0.0f;
#pragma unroll
    for (int pb = 0; pb < NUM_PROTOS; pb += 16) {
        float v[16];
#pragma unroll
        for (int i = 0; i < 16; ++i)
            v[i] = __ldcg(&w[(size_t)(((pb + i) << 3) + l) * D_DIM + d]);
#pragma unroll
        for (int i = 0; i < 16; ++i) {
            sum += v[i];
            sq  += v[i] * v[i];
        }
    }
    g_c[l * D_DIM + d] = sum * (1.0f / NUM_PROTOS);

    // block-reduce sq (warp shuffle + smem, fixed order)
    const unsigned FULL = 0xFFFFFFFFu;
#pragma unroll
    for (int off = 16; off > 0; off >>= 1)
        sq += __shfl_xor_sync(FULL, sq, off);

    __shared__ float red[8];
    if ((threadIdx.x & 31) == 0) red[threadIdx.x >> 5] = sq;
    __syncthreads();
    if (threadIdx.x == 0) {
        float t = 0.0f;
#pragma unroll
        for (int ww = 0; ww < 8; ++ww) t += red[ww];
        g_sqpart[blockIdx.x] = t;
    }
}

// ---------------------------------------------------------------------------
// Main: one block per batch row b (identical to the 154.9us R1/R2 kernel).
//   a[b,:] = (1/T) sum_t h[b,t,:]        (streamed, 256 KB per block)
//   out[b,l] = 2 * a.c_l - ||a||^2 - s_l
// Streaming phase is independent of the fold; cudaGridDependencySynchronize()
// only before the epilogue reads g_c/g_sqpart.
// ---------------------------------------------------------------------------
__global__ __launch_bounds__(256, 8)
void pool_proto_kernel(const float* __restrict__ h, float* __restrict__ out) {
    const int b   = blockIdx.x;
    const int tid = threadIdx.x;

    const float4* hp = reinterpret_cast<const float4*>(h)
                       + (size_t)b * T_DIM * (D_DIM / 4) + tid;

    float4 s0 = {0,0,0,0}, s1 = {0,0,0,0}, s2 = {0,0,0,0}, s3 = {0,0,0,0};

#pragma unroll 4
    for (int t = 0; t < T_DIM; t += 8) {
        float4 v0 = __ldcs(hp + (size_t)(t + 0) * 256);
        float4 v1 = __ldcs(hp + (size_t)(t + 1) * 256);
        float4 v2 = __ldcs(hp + (size_t)(t + 2) * 256);
        float4 v3 = __ldcs(hp + (size_t)(t + 3) * 256);
        float4 v4 = __ldcs(hp + (size_t)(t + 4) * 256);
        float4 v5 = __ldcs(hp + (size_t)(t + 5) * 256);
        float4 v6 = __ldcs(hp + (size_t)(t + 6) * 256);
        float4 v7 = __ldcs(hp + (size_t)(t + 7) * 256);
        s0.x += v0.x; s0.y += v0.y; s0.z += v0.z; s0.w += v0.w;
        s1.x += v1.x; s1.y += v1.y; s1.z += v1.z; s1.w += v1.w;
        s2.x += v2.x; s2.y += v2.y; s2.z += v2.z; s2.w += v2.w;
        s3.x += v3.x; s3.y += v3.y; s3.z += v3.z; s3.w += v3.w;
        s0.x += v4.x; s0.y += v4.y; s0.z += v4.z; s0.w += v4.w;
        s1.x += v5.x; s1.y += v5.y; s1.z += v5.z; s1.w += v5.w;
        s2.x += v6.x; s2.y += v6.y; s2.z += v6.z; s2.w += v6.w;
        s3.x += v7.x; s3.y += v7.y; s3.z += v7.z; s3.w += v7.w;
    }

    const float inv_t = 1.0f / T_DIM;
    float4 a;
    a.x = (s0.x + s1.x + s2.x + s3.x) * inv_t;
    a.y = (s0.y + s1.y + s2.y + s3.y) * inv_t;
    a.z = (s0.z + s1.z + s2.z + s3.z) * inv_t;
    a.w = (s0.w + s1.w + s2.w + s3.w) * inv_t;

    float asq = a.x * a.x + a.y * a.y + a.z * a.z + a.w * a.w;

    // Fold results ready long ago; PDL dependency resolves instantly here.
    cudaGridDependencySynchronize();

    float dot[NUM_LABELS];
#pragma unroll
    for (int l = 0; l < NUM_LABELS; ++l) {
        float4 cv = reinterpret_cast<const float4*>(g_c + l * D_DIM)[tid];
        dot[l] = a.x * cv.x + a.y * cv.y + a.z * cv.z + a.w * cv.w;
    }

    const unsigned FULL = 0xFFFFFFFFu;
#pragma unroll
    for (int off = 16; off > 0; off >>= 1) {
        asq += __shfl_xor_sync(FULL, asq, off);
#pragma unroll
        for (int l = 0; l < NUM_LABELS; ++l)
            dot[l] += __shfl_xor_sync(FULL, dot[l], off);
    }

    __shared__ float part[8][12];  // 8 warps x (8 dots + asq), padded
    const int wid = tid >> 5;
    if ((tid & 31) == 0) {
#pragma unroll
        for (int l = 0; l < NUM_LABELS; ++l) part[wid][l] = dot[l];
        part[wid][8] = asq;
    }
    __syncthreads();

    if (tid < NUM_LABELS) {
        const int l = tid;
        float dl = 0.0f, aq = 0.0f;
#pragma unroll
        for (int w = 0; w < 8; ++w) {
            dl += part[w][l];
            aq += part[w][8];
        }
        float sl = (g_sqpart[l * 4 + 0] + g_sqpart[l * 4 + 1] +
                    g_sqpart[l * 4 + 2] + g_sqpart[l * 4 + 3]) * (1.0f / NUM_PROTOS);
        out[(size_t)b * NUM_LABELS + l] = 2.0f * dl - aq - sl;
    }
}

extern "C" void kernel_launch(void* const* d_in, const int* in_sizes, int n_in,
                              void* d_out, int out_size) {
    const float* h = (const float*)d_in[0];   // hidden_states [B, T, D]
    const float* w = (const float*)d_in[1];   // prototype_weight [512, D]
    float* out = (float*)d_out;               // [B, 8]

    // Fold kernel: launched first; clears its SMs in ~2.5us.
    proto_fold_kernel<<<32, 256>>>(w);

    // Pool kernel with PDL: starts streaming immediately (overlapping the
    // fold), syncs on the fold only at the epilogue.
    cudaLaunchConfig_t cfg = {};
    cfg.gridDim  = dim3(B_DIM);
    cfg.blockDim = dim3(256);
    cfg.dynamicSmemBytes = 0;
    cfg.stream = 0;

    cudaLaunchAttribute attrs[1];
    attrs[0].id = cudaLaunchAttributeProgrammaticStreamSerialization;
    attrs[0].val.programmaticStreamSerializationAllowed = 1;
    cfg.attrs = attrs;
    cfg.numAttrs = 1;

    cudaLaunchKernelEx(&cfg, pool_proto_kernel, h, out);
}

// round 7
// speedup vs baseline: 1.0924x; 1.0175x over previous
#include <cuda_runtime.h>
#include <cstdint>

// Problem constants (fixed by the reference)
#define B_DIM 1024
#define T_DIM 256
#define D_DIM 1024
#define NUM_LABELS 8
#define NUM_PROTOS 64   // per label; M = 512 total

#define FOLD_BLOCKS 64  // 8 labels x 8 d-segments of 128

// Device scratch (no cudaMalloc allowed)
__device__ float g_c[NUM_LABELS * D_DIM];  // c_l[d] = mean_p w[8p+l][d]  (32 KB)
__device__ float g_sq64[FOLD_BLOCKS];      // per (l,seg) partial sum of w^2
__device__ unsigned g_done;                // fold-done counter (memset per launch)

// ---------------------------------------------------------------------------
// Fused kernel, grid 1024 x 256. Block b streams batch row b.
// Blocks 0..63 additionally run a ~1us COALESCED fold prologue first:
//   block = (l = bid>>3, seg = bid&7); thread pair (tid>>1 = d-in-seg,
//   tid&1 = which 32 prototypes). 32 loads each, batched 16-wide, __ldcg.
//   Pair-combine via shfl_xor(1) (fp32 add commutative -> bit-exact on both
//   lanes); block-reduces sq (each d counted twice; *0.5f is exact scaling).
// Epilogue of every block spins on g_done==64 — satisfied ~154us earlier.
// Deadlock-free in any wave structure: fold blocks (bid 0..63) are wave-1;
// spinners depend only on them.
// ---------------------------------------------------------------------------
__global__ __launch_bounds__(256, 8)
void fused_pool_proto_kernel(const float* __restrict__ h,
                             const float* __restrict__ w,
                             float* __restrict__ out) {
    const int b    = blockIdx.x;
    const int tid  = threadIdx.x;
    const int wid  = tid >> 5;
    const int lane = tid & 31;
    const unsigned FULL = 0xFFFFFFFFu;

    // ---- Fold prologue (blocks 0..63 only) ----
    if (b < FOLD_BLOCKS) {
        const int l   = b >> 3;
        const int seg = b & 7;
        const int d   = seg * 128 + (tid >> 1);
        const int ph  = tid & 1;            // which half of the 64 prototypes

        float sum = 0.0f, sq = 0.0f;
#pragma unroll
        for (int pb = 0; pb < 32; pb += 16) {
            float v[16];
#pragma unroll
            for (int i = 0; i < 16; ++i)
                v[i] = __ldcg(&w[(size_t)(((ph * 32 + pb + i) << 3) + l) * D_DIM + d]);
#pragma unroll
            for (int i = 0; i < 16; ++i) {
                sum += v[i];
                sq  += v[i] * v[i];
            }
        }
        // Combine the two p-halves of this d (commutative -> identical on both lanes)
        sum += __shfl_xor_sync(FULL, sum, 1);
        sq  += __shfl_xor_sync(FULL, sq,  1);
        if (ph == 0) g_c[l * D_DIM + d] = sum * (1.0f / NUM_PROTOS);

        // Block-reduce sq over the 128 d's (each counted twice; fixed order)
#pragma unroll
        for (int off = 16; off > 0; off >>= 1)
            sq += __shfl_xor_sync(FULL, sq, off);
        __shared__ float red[8];
        if (lane == 0) red[wid] = sq;
        __syncthreads();
        if (tid == 0) {
            float t = 0.0f;
#pragma unroll
            for (int ww = 0; ww < 8; ++ww) t += red[ww];
            g_sq64[b] = t * 0.5f;           // undo the double count (exact)
            __threadfence();
            atomicAdd(&g_done, 1u);
        }
        __syncthreads();
    }

    // ---- Streaming phase (identical to the 154.9us loop) ----
    const float4* hp = reinterpret_cast<const float4*>(h)
                       + (size_t)b * T_DIM * (D_DIM / 4) + tid;

    float4 s0 = {0,0,0,0}, s1 = {0,0,0,0}, s2 = {0,0,0,0}, s3 = {0,0,0,0};
#pragma unroll 4
    for (int t = 0; t < T_DIM; t += 8) {
        float4 v0 = __ldcs(hp + (size_t)(t + 0) * 256);
        float4 v1 = __ldcs(hp + (size_t)(t + 1) * 256);
        float4 v2 = __ldcs(hp + (size_t)(t + 2) * 256);
        float4 v3 = __ldcs(hp + (size_t)(t + 3) * 256);
        float4 v4 = __ldcs(hp + (size_t)(t + 4) * 256);
        float4 v5 = __ldcs(hp + (size_t)(t + 5) * 256);
        float4 v6 = __ldcs(hp + (size_t)(t + 6) * 256);
        float4 v7 = __ldcs(hp + (size_t)(t + 7) * 256);
        s0.x += v0.x; s0.y += v0.y; s0.z += v0.z; s0.w += v0.w;
        s1.x += v1.x; s1.y += v1.y; s1.z += v1.z; s1.w += v1.w;
        s2.x += v2.x; s2.y += v2.y; s2.z += v2.z; s2.w += v2.w;
        s3.x += v3.x; s3.y += v3.y; s3.z += v3.z; s3.w += v3.w;
        s0.x += v4.x; s0.y += v4.y; s0.z += v4.z; s0.w += v4.w;
        s1.x += v5.x; s1.y += v5.y; s1.z += v5.z; s1.w += v5.w;
        s2.x += v6.x; s2.y += v6.y; s2.z += v6.z; s2.w += v6.w;
        s3.x += v7.x; s3.y += v7.y; s3.z += v7.z; s3.w += v7.w;
    }

    const float inv_t = 1.0f / T_DIM;
    float4 a;
    a.x = (s0.x + s1.x + s2.x + s3.x) * inv_t;
    a.y = (s0.y + s1.y + s2.y + s3.y) * inv_t;
    a.z = (s0.z + s1.z + s2.z + s3.z) * inv_t;
    a.w = (s0.w + s1.w + s2.w + s3.w) * inv_t;

    float asq = a.x * a.x + a.y * a.y + a.z * a.z + a.w * a.w;

    // ---- Wait for fold (satisfied ~154us ago -> first poll succeeds) ----
    if (tid == 0) {
        while (atomicAdd(&g_done, 0u) < (unsigned)FOLD_BLOCKS) {}
    }
    __syncthreads();
    __threadfence();

    // ---- Epilogue: 8 dots vs c_l + reductions ----
    float dot[NUM_LABELS];
#pragma unroll
    for (int l = 0; l < NUM_LABELS; ++l) {
        float4 cv = reinterpret_cast<const float4*>(g_c + l * D_DIM)[tid];
        dot[l] = a.x * cv.x + a.y * cv.y + a.z * cv.z + a.w * cv.w;
    }

#pragma unroll
    for (int off = 16; off > 0; off >>= 1) {
        asq += __shfl_xor_sync(FULL, asq, off);
#pragma unroll
        for (int l = 0; l < NUM_LABELS; ++l)
            dot[l] += __shfl_xor_sync(FULL, dot[l], off);
    }

    __shared__ float part[8][12];  // 8 warps x (8 dots + asq), padded
    if (lane == 0) {
#pragma unroll
        for (int l = 0; l < NUM_LABELS; ++l) part[wid][l] = dot[l];
        part[wid][8] = asq;
    }
    __syncthreads();

    if (tid < NUM_LABELS) {
        const int l = tid;
        float dl = 0.0f, aq = 0.0f;
#pragma unroll
        for (int ww = 0; ww < 8; ++ww) {
            dl += part[ww][l];
            aq += part[ww][8];
        }
        float sl = 0.0f;
#pragma unroll
        for (int seg = 0; seg < 8; ++seg) sl += g_sq64[l * 8 + seg];
        sl *= (1.0f / NUM_PROTOS);
        out[(size_t)b * NUM_LABELS + l] = 2.0f * dl - aq - sl;
    }
}

extern "C" void kernel_launch(void* const* d_in, const int* in_sizes, int n_in,
                              void* d_out, int out_size) {
    const float* h = (const float*)d_in[0];   // hidden_states [B, T, D]
    const float* w = (const float*)d_in[1];   // prototype_weight [512, D]
    float* out = (float*)d_out;               // [B, 8]

    // Reset the fold-done counter (graph-capturable async memset).
    void* done_addr = nullptr;
    cudaGetSymbolAddress(&done_addr, g_done);
    cudaMemsetAsync(done_addr, 0, sizeof(unsigned), 0);

    fused_pool_proto_kernel<<<B_DIM, 256>>>(h, w, out);
}